// round 16
// baseline (speedup 1.0000x reference)
#include <cuda_runtime.h>
#include <cuda_fp16.h>
#include <math.h>
#include <stdint.h>

#define BATCH  2
#define SEQ    2048
#define DMODEL 1024
#define NH     16
#define HD     64
#define M_ROWS (BATCH * SEQ)    // 4096
#define QKV_N  (3 * DMODEL)     // 3072

// ---------------------------------------------------------------------------
// Device scratch (fp16 emulation: A-side split hi/lo, B-side hi only)
// ---------------------------------------------------------------------------
__device__ __half g_xh[M_ROWS * DMODEL];
__device__ __half g_xl[M_ROWS * DMODEL];
__device__ __half g_wqh[QKV_N * DMODEL];   // [N,K] transposed, hi only
__device__ __half g_woh[DMODEL * DMODEL];  // [N,K] transposed, hi only
__device__ __half g_ah[M_ROWS * DMODEL];   // attention out hi (A of out-proj)
__device__ __half g_al[M_ROWS * DMODEL];

#define QKV_ELEMS (BATCH * NH * SEQ * HD)
__device__ __half g_qh[QKV_ELEMS];  // [B,H,S,hd], pre-scaled by 1/8
__device__ __half g_ql[QKV_ELEMS];
__device__ __half g_kh[QKV_ELEMS];  // hi only (B operand of QK^T)
__device__ __half g_vh[QKV_ELEMS];  // hi only (B operand of PV)

__device__ float2 g_rope_tab[SEQ * 32];    // (cos, sin) per (s, j)

// ---------------------------------------------------------------------------
// Baseline-PTX helpers
// ---------------------------------------------------------------------------
__device__ __forceinline__ uint32_t smem_u32(const void* p) {
    uint32_t a;
    asm("{ .reg .u64 t; cvta.to.shared.u64 t, %1; cvt.u32.u64 %0, t; }"
        : "=r"(a) : "l"(p));
    return a;
}

#define CP_ASYNC_16(smem, gptr) \
    asm volatile("cp.async.cg.shared.global [%0], [%1], 16;\n" \
        :: "r"(smem), "l"(gptr))
#define CP_ASYNC_COMMIT() asm volatile("cp.async.commit_group;\n")
#define CP_ASYNC_WAIT(n)  asm volatile("cp.async.wait_group %0;\n" :: "n"(n))

__device__ __forceinline__ void ldsm_x4(uint32_t* r, uint32_t addr) {
    asm volatile("ldmatrix.sync.aligned.m8n8.x4.shared.b16 {%0,%1,%2,%3}, [%4];\n"
        : "=r"(r[0]), "=r"(r[1]), "=r"(r[2]), "=r"(r[3]) : "r"(addr));
}
__device__ __forceinline__ void ldsm_x4_t(uint32_t* r, uint32_t addr) {
    asm volatile("ldmatrix.sync.aligned.m8n8.x4.trans.shared.b16 {%0,%1,%2,%3}, [%4];\n"
        : "=r"(r[0]), "=r"(r[1]), "=r"(r[2]), "=r"(r[3]) : "r"(addr));
}

// D(f32) += A(f16) * B(f16): m16n8k16
__device__ __forceinline__ void mma16816(float* d, const uint32_t* a, const uint32_t* b) {
    asm volatile(
        "mma.sync.aligned.m16n8k16.row.col.f32.f16.f16.f32 "
        "{%0,%1,%2,%3}, {%4,%5,%6,%7}, {%8,%9}, {%0,%1,%2,%3};\n"
        : "+f"(d[0]), "+f"(d[1]), "+f"(d[2]), "+f"(d[3])
        : "r"(a[0]), "r"(a[1]), "r"(a[2]), "r"(a[3]), "r"(b[0]), "r"(b[1]));
}

// 128B-row swizzle: 16B chunk (0..7) xor bits [2:0] of row
__device__ __forceinline__ uint32_t aswz(int row, int chunk) {
    return (uint32_t)(row * 128 + ((chunk ^ (row & 7)) << 4));
}

// ---------------------------------------------------------------------------
// fp32 -> (hi, lo) fp16 split helpers
// ---------------------------------------------------------------------------
__device__ __forceinline__ void split2(float x, __half& h, __half& l) {
    h = __float2half(x);
    l = __float2half(x - __half2float(h));
}
__device__ __forceinline__ uint32_t pack_h2(__half a, __half b) {
    __half2 t; t.x = a; t.y = b;
    return *(uint32_t*)&t;
}

// ---------------------------------------------------------------------------
// Fused prep (unchanged)
// ---------------------------------------------------------------------------
#define PREP_CONV_BLOCKS  4096
#define PREP_TRANS_BLOCKS 4096
#define PREP_ROPE_BLOCKS  256
#define PREP_BLOCKS (PREP_CONV_BLOCKS + PREP_TRANS_BLOCKS + PREP_ROPE_BLOCKS)

__global__ void __launch_bounds__(256)
prep_kernel(const float4* __restrict__ x4,
            const float* __restrict__ Wq, const float* __restrict__ Wo,
            uint2* __restrict__ xh, uint2* __restrict__ xl,
            __half* __restrict__ Tq, __half* __restrict__ To,
            float2* __restrict__ tab)
{
    const int blk = blockIdx.x;
    const int tid = threadIdx.x;

    if (blk < PREP_CONV_BLOCKS) {
        int i = blk * 256 + tid;
        float4 v = x4[i];
        __half h0, l0, h1, l1, h2, l2, h3, l3;
        split2(v.x, h0, l0); split2(v.y, h1, l1);
        split2(v.z, h2, l2); split2(v.w, h3, l3);
        xh[i] = make_uint2(pack_h2(h0, h1), pack_h2(h2, h3));
        xl[i] = make_uint2(pack_h2(l0, l1), pack_h2(l2, l3));
    } else if (blk < PREP_CONV_BLOCKS + PREP_TRANS_BLOCKS) {
        __shared__ float tile[32][33];
        const int t = blk - PREP_CONV_BLOCKS;
        const int tile_n = t & 127;
        const int tile_k = t >> 7;
        const int tx = tid & 31;
        const int ty0 = tid >> 5;
        const int n = tile_n * 32 + tx;
#pragma unroll
        for (int r = 0; r < 4; r++) {
            const int ty = ty0 + r * 8;
            const int k = tile_k * 32 + ty;
            float v = (n < QKV_N) ? Wq[(size_t)k * QKV_N + n]
                                  : Wo[(size_t)k * DMODEL + (n - QKV_N)];
            tile[ty][tx] = v;
        }
        __syncthreads();
#pragma unroll
        for (int r = 0; r < 4; r++) {
            const int ty = ty0 + r * 8;
            const int nt = tile_n * 32 + ty;
            const int kt = tile_k * 32 + tx;
            __half hv = __float2half(tile[tx][ty]);
            if (nt < QKV_N) Tq[(size_t)nt * DMODEL + kt] = hv;
            else            To[(size_t)(nt - QKV_N) * DMODEL + kt] = hv;
        }
    } else {
        int i = (blk - PREP_CONV_BLOCKS - PREP_TRANS_BLOCKS) * 256 + tid;
        int j = i & 31, s = i >> 5;
        float inv_freq = powf(10000.0f, -(float)j * (1.0f / 32.0f));
        float sn, cs;
        sincosf((float)s * inv_freq, &sn, &cs);
        tab[i] = make_float2(cs, sn);
    }
}

// ---------------------------------------------------------------------------
// Tensor-core GEMM, templated on BM (CTA M-tile).
// BM=256 (QKV): 8 warps 4m x 2n, warp tile 64x64 -> 96 B smem/MMA (74% ceiling)
// BM=128 (out-proj): 8 warps 4m x 2n, warp tile 32x64 (R15 config)
// BK=64, double-buffered cp.async. fp16 x 2-term fp32 emulation.
// mode 0: store fp32 C.  mode 1: fused in-register RoPE/split epilogue.
// ---------------------------------------------------------------------------
#define G_BK 64

template <int BM>
__global__ void __launch_bounds__(256)
gemm_fp16x2_kernel(const __half* __restrict__ Ahi,
                   const __half* __restrict__ Alo,
                   const __half* __restrict__ Bh,
                   float* __restrict__ C,
                   __half* __restrict__ qh, __half* __restrict__ ql,
                   __half* __restrict__ kh, __half* __restrict__ vh,
                   int M, int N, int K, int mode)
{
    constexpr int MT = BM / 64;                 // 16-row tiles per warp: 2 or 4
    constexpr int A_TILE_B = BM * 128;          // BM rows x 64 halfs
    constexpr int B_TILE_B = 128 * 128;         // 16384
    constexpr int STAGE_B  = 2 * A_TILE_B + B_TILE_B;
    constexpr int ALOADS   = BM * 8;            // 16B loads per A tile
    constexpr int NLOADS   = (2 * ALOADS + 1024) / 256;

    extern __shared__ __align__(128) char dsm[];
    const uint32_t smem_base = smem_u32(dsm);

    const int tid = threadIdx.x;
    const int wid = tid >> 5;          // 0..7
    const int lane = tid & 31;
    const int warp_m = wid >> 1;       // 0..3 -> (BM/4)-row slice
    const int warp_n = wid & 1;        // 0..1 -> 64-col slice
    const int m0 = blockIdx.y * BM;
    const int n0 = blockIdx.x * 128;

    float acc[MT][8][4];
#pragma unroll
    for (int i = 0; i < MT; i++)
#pragma unroll
        for (int j = 0; j < 8; j++)
#pragma unroll
            for (int c = 0; c < 4; c++) acc[i][j][c] = 0.f;

    const int nchunk = K / G_BK;       // 16

    auto issue = [&](int ci) {
        const int k0 = ci * G_BK;
        const uint32_t st = smem_base + (ci & 1) * STAGE_B;
#pragma unroll
        for (int i = 0; i < NLOADS; i++) {
            int idx = (i << 8) | tid;
            const __half* src;
            uint32_t toff;
            int base_row;
            if (idx < ALOADS)          { src = Ahi; toff = 0;            base_row = m0; }
            else if (idx < 2 * ALOADS) { idx -= ALOADS; src = Alo; toff = A_TILE_B; base_row = m0; }
            else                       { idx -= 2 * ALOADS; src = Bh; toff = 2 * A_TILE_B; base_row = n0; }
            const int r = idx >> 3, c = idx & 7;
            CP_ASYNC_16(st + toff + aswz(r, c),
                        src + (size_t)(base_row + r) * K + k0 + c * 8);
        }
        CP_ASYNC_COMMIT();
    };

    issue(0);

    const int a_row_off = (lane & 15);
    const int a_coff    = (lane >> 4) & 1;
    const int b_row_off = ((lane & 16) >> 1) + (lane & 7);
    const int b_coff    = (lane & 8) >> 3;

#pragma unroll 1
    for (int ci = 0; ci < nchunk; ci++) {
        CP_ASYNC_WAIT(0);
        __syncthreads();
        if (ci + 1 < nchunk) issue(ci + 1);

        const uint32_t st = smem_base + (ci & 1) * STAGE_B;
        const uint32_t sAhi = st;
        const uint32_t sAlo = st + A_TILE_B;
        const uint32_t sBh  = st + 2 * A_TILE_B;

#pragma unroll
        for (int ks = 0; ks < 4; ks++) {
            uint32_t ahi[MT][4], alo[MT][4];
#pragma unroll
            for (int mt = 0; mt < MT; mt++) {
                const int ar = warp_m * (BM / 4) + mt * 16 + a_row_off;
                const uint32_t aoff = aswz(ar, ks * 2 + a_coff);
                ldsm_x4(ahi[mt], sAhi + aoff);
                ldsm_x4(alo[mt], sAlo + aoff);
            }
#pragma unroll
            for (int ntp = 0; ntp < 4; ntp++) {
                const int br = warp_n * 64 + ntp * 16 + b_row_off;
                const uint32_t boff = aswz(br, ks * 2 + b_coff);
                uint32_t bh4[4];
                ldsm_x4(bh4, sBh + boff);
#pragma unroll
                for (int mt = 0; mt < MT; mt++)
#pragma unroll
                    for (int j = 0; j < 2; j++) {
                        float* d = acc[mt][2 * ntp + j];
                        mma16816(d, ahi[mt], &bh4[2 * j]);
                        mma16816(d, alo[mt], &bh4[2 * j]);
                    }
            }
        }
    }

    const int quad = lane >> 2;
    const int tq = lane & 3;

    if (mode == 0) {
        float* Cw = C + (size_t)(m0 + warp_m * (BM / 4)) * N + n0 + warp_n * 64;
#pragma unroll
        for (int mt = 0; mt < MT; mt++)
#pragma unroll
            for (int nt = 0; nt < 8; nt++) {
                const int r = mt * 16 + quad;
                const int c = nt * 8 + tq * 2;
                *(float2*)(Cw + (size_t)r * N + c) =
                    make_float2(acc[mt][nt][0], acc[mt][nt][1]);
                *(float2*)(Cw + (size_t)(r + 8) * N + c) =
                    make_float2(acc[mt][nt][2], acc[mt][nt][3]);
            }
        return;
    }

    // ---- mode 1: fused RoPE + split epilogue for QKV ----
    const int ng0 = n0 + warp_n * 64;          // 64-aligned -> single head
    const int sec = ng0 >> 10;                 // 0=q, 1=k, 2=v
    const int hh  = (ng0 & 1023) >> 6;
    __half* ph = (sec == 0) ? qh : (sec == 1) ? kh : vh;

#pragma unroll
    for (int mt = 0; mt < MT; mt++) {
#pragma unroll
        for (int half = 0; half < 2; half++) {
            const int r_g = m0 + warp_m * (BM / 4) + mt * 16 + quad + half * 8;
            const int b = r_g >> 11, s = r_g & 2047;
            const size_t dst = ((size_t)((b * NH + hh) * SEQ) + s) * HD;
            const float2* trow = g_rope_tab + s * 32;
#pragma unroll
            for (int nt = 0; nt < 8; nt++) {
                const int d0 = nt * 8 + tq * 2;
                float v0 = acc[mt][nt][half * 2 + 0];
                float v1 = acc[mt][nt][half * 2 + 1];
                float r0, r1;
                if (sec < 2) {
                    const float p0 = acc[mt][nt ^ 4][half * 2 + 0];
                    const float p1 = acc[mt][nt ^ 4][half * 2 + 1];
                    const int j0 = d0 & 31;
                    const float2 t0 = trow[j0];
                    const float2 t1 = trow[j0 + 1];
                    if (nt < 4) { r0 = v0 * t0.x - p0 * t0.y; r1 = v1 * t1.x - p1 * t1.y; }
                    else        { r0 = v0 * t0.x + p0 * t0.y; r1 = v1 * t1.x + p1 * t1.y; }
                    if (sec == 0) { r0 *= 0.125f; r1 *= 0.125f; }
                } else { r0 = v0; r1 = v1; }
                if (sec == 0) {
                    __half h0, e0, h1, e1;
                    split2(r0, h0, e0);
                    split2(r1, h1, e1);
                    *(uint32_t*)(qh + dst + d0) = pack_h2(h0, h1);
                    *(uint32_t*)(ql + dst + d0) = pack_h2(e0, e1);
                } else {
                    *(uint32_t*)(ph + dst + d0) =
                        pack_h2(__float2half(r0), __float2half(r1));
                }
            }
        }
    }
}

#define G_SMEM_256 (2 * (2 * 256 * 128 + 128 * 128))   // 163840
#define G_SMEM_128 (2 * (2 * 128 * 128 + 128 * 128))   // 98304

// ---------------------------------------------------------------------------
// Tensor-core causal flash attention (unchanged from R15)
// ---------------------------------------------------------------------------
#define AT_TILE_B  (64 * 128)
#define AT_STAGE_B (2 * AT_TILE_B)
#define AT_STAGES  3
#define AT_SMEM_B  (AT_STAGES * AT_STAGE_B)

__global__ void __launch_bounds__(256)
attn_tc_kernel(const __half* __restrict__ qh, const __half* __restrict__ ql,
               const __half* __restrict__ kh, const __half* __restrict__ vh,
               __half* __restrict__ outh, __half* __restrict__ outl)
{
    extern __shared__ __align__(128) char dsm[];
    const uint32_t sb = smem_u32(dsm);

    const int bh = blockIdx.y;
    const int tid = threadIdx.x;
    const int wid = tid >> 5;
    const int lane = tid & 31;
    const int kq = (lane & 3) * 2;
    const size_t base = (size_t)bh * SEQ * HD;

    const __half* khp = kh + base;
    const __half* vhp = vh + base;

    auto issue = [&](int kt) {
        const uint32_t st = sb + (kt % AT_STAGES) * AT_STAGE_B;
        const __half* srcs[2] = {khp, vhp};
        const int kr0 = kt * 64;
#pragma unroll
        for (int t = 0; t < 2; t++) {
#pragma unroll
            for (int i = 0; i < 2; i++) {
                int c = i * 256 + tid;
                int row = c >> 3, col = c & 7;
                CP_ASYNC_16(st + t * AT_TILE_B + aswz(row, col),
                            srcs[t] + (size_t)(kr0 + row) * HD + col * 8);
            }
        }
        CP_ASYNC_COMMIT();
    };

    const int b_row = ((lane & 16) >> 1) + (lane & 7);
    const int b_coff = (lane & 8) >> 3;
    const int vg    = lane >> 3;
    const int rloc = wid * 16 + (lane >> 2);

#pragma unroll 1
    for (int ps = 0; ps < 2; ps++) {
        const int qt = ps ? (int)blockIdx.x : (SEQ / 128 - 1 - (int)blockIdx.x);
        const int grow = qt * 128 + rloc;

        uint32_t qfh[4][4], qfl[4][4];
#pragma unroll
        for (int kc = 0; kc < 4; kc++) {
            size_t o = base + (size_t)grow * HD + kc * 16 + kq;
            qfh[kc][0] = *(const uint32_t*)(qh + o);
            qfh[kc][1] = *(const uint32_t*)(qh + o + 8 * HD);
            qfh[kc][2] = *(const uint32_t*)(qh + o + 8);
            qfh[kc][3] = *(const uint32_t*)(qh + o + 8 * HD + 8);
            qfl[kc][0] = *(const uint32_t*)(ql + o);
            qfl[kc][1] = *(const uint32_t*)(ql + o + 8 * HD);
            qfl[kc][2] = *(const uint32_t*)(ql + o + 8);
            qfl[kc][3] = *(const uint32_t*)(ql + o + 8 * HD + 8);
        }

        float oa[8][4];
#pragma unroll
        for (int i = 0; i < 8; i++)
#pragma unroll
            for (int c = 0; c < 4; c++) oa[i][c] = 0.f;
        float m0 = -INFINITY, m1 = -INFINITY, l0 = 0.f, l1 = 0.f;

        const int nkt = 2 * qt + 2;

        __syncthreads();
        issue(0);
        if (nkt > 1) issue(1);

#pragma unroll 1
        for (int kt = 0; kt < nkt; kt++) {
            if (kt + 1 < nkt) { CP_ASYNC_WAIT(1); } else { CP_ASYNC_WAIT(0); }
            __syncthreads();
            if (kt + 2 < nkt) issue(kt + 2);

            const int tile_k0 = kt * 64;
            const int wrow_min = qt * 128 + wid * 16;
            const bool full_skip = tile_k0 > wrow_min + 15;
            const bool need_mask = !full_skip && (tile_k0 + 63 > wrow_min);

            if (!full_skip) {
                const uint32_t st  = sb + (kt % AT_STAGES) * AT_STAGE_B;
                const uint32_t sKh = st;
                const uint32_t sVh = st + AT_TILE_B;

                float sacc[8][4];
#pragma unroll
                for (int i = 0; i < 8; i++)
#pragma unroll
                    for (int c = 0; c < 4; c++) sacc[i][c] = 0.f;

#pragma unroll
                for (int kc = 0; kc < 4; kc++) {
#pragma unroll
                    for (int np = 0; np < 4; np++) {
                        const int krow = np * 16 + b_row;
                        const uint32_t addr = aswz(krow, kc * 2 + b_coff);
                        uint32_t bh4[4];
                        ldsm_x4(bh4, sKh + addr);
#pragma unroll
                        for (int j = 0; j < 2; j++) {
                            float* d = sacc[2 * np + j];
                            mma16816(d, qfh[kc], &bh4[2 * j]);
                            mma16816(d, qfl[kc], &bh4[2 * j]);
                        }
                    }
                }

                if (need_mask) {
#pragma unroll
                    for (int nt = 0; nt < 8; nt++) {
                        const int colg = tile_k0 + nt * 8 + kq;
                        if (colg > grow)         sacc[nt][0] = -INFINITY;
                        if (colg + 1 > grow)     sacc[nt][1] = -INFINITY;
                        if (colg > grow + 8)     sacc[nt][2] = -INFINITY;
                        if (colg + 1 > grow + 8) sacc[nt][3] = -INFINITY;
                    }
                }

                float rm0 = -INFINITY, rm1 = -INFINITY;
#pragma unroll
                for (int nt = 0; nt < 8; nt++) {
                    rm0 = fmaxf(rm0, fmaxf(sacc[nt][0], sacc[nt][1]));
                    rm1 = fmaxf(rm1, fmaxf(sacc[nt][2], sacc[nt][3]));
                }
                rm0 = fmaxf(rm0, __shfl_xor_sync(0xffffffffu, rm0, 1));
                rm0 = fmaxf(rm0, __shfl_xor_sync(0xffffffffu, rm0, 2));
                rm1 = fmaxf(rm1, __shfl_xor_sync(0xffffffffu, rm1, 1));
                rm1 = fmaxf(rm1, __shfl_xor_sync(0xffffffffu, rm1, 2));

                float mn0 = fmaxf(m0, rm0), mn1 = fmaxf(m1, rm1);
                float c0 = __expf(m0 - mn0), c1 = __expf(m1 - mn1);
                m0 = mn0; m1 = mn1;
                l0 *= c0; l1 *= c1;
#pragma unroll
                for (int nt = 0; nt < 8; nt++) {
                    oa[nt][0] *= c0; oa[nt][1] *= c0;
                    oa[nt][2] *= c1; oa[nt][3] *= c1;
                }

                float ps0 = 0.f, ps1 = 0.f;
#pragma unroll
                for (int kc2 = 0; kc2 < 4; kc2++) {
                    uint32_t pfh[4], pfl[4];
#pragma unroll
                    for (int j = 0; j < 2; j++) {
                        const int t = 2 * kc2 + j;
                        float p0 = __expf(sacc[t][0] - m0);
                        float p1 = __expf(sacc[t][1] - m0);
                        float p2 = __expf(sacc[t][2] - m1);
                        float p3 = __expf(sacc[t][3] - m1);
                        ps0 += p0 + p1; ps1 += p2 + p3;
                        __half h0, e0, h1, e1, h2, e2, h3, e3;
                        split2(p0, h0, e0); split2(p1, h1, e1);
                        split2(p2, h2, e2); split2(p3, h3, e3);
                        pfh[2 * j]     = pack_h2(h0, h1);
                        pfh[2 * j + 1] = pack_h2(h2, h3);
                        pfl[2 * j]     = pack_h2(e0, e1);
                        pfl[2 * j + 1] = pack_h2(e2, e3);
                    }
#pragma unroll
                    for (int dp = 0; dp < 4; dp++) {
                        const int vrow = kc2 * 16 + (lane & 7) + ((vg & 1) << 3);
                        const uint32_t addr = aswz(vrow, dp * 2 + (vg >> 1));
                        uint32_t bvh[4];
                        ldsm_x4_t(bvh, sVh + addr);
#pragma unroll
                        for (int j = 0; j < 2; j++) {
                            float* d = oa[2 * dp + j];
                            mma16816(d, pfh, &bvh[2 * j]);
                            mma16816(d, pfl, &bvh[2 * j]);
                        }
                    }
                }
                ps0 += __shfl_xor_sync(0xffffffffu, ps0, 1);
                ps0 += __shfl_xor_sync(0xffffffffu, ps0, 2);
                ps1 += __shfl_xor_sync(0xffffffffu, ps1, 1);
                ps1 += __shfl_xor_sync(0xffffffffu, ps1, 2);
                l0 += ps0; l1 += ps1;
            }
        }

        const float il0 = 1.0f / l0, il1 = 1.0f / l1;
        const int b = bh >> 4, h = bh & 15;
        const int s0 = qt * 128 + wid * 16 + (lane >> 2);
        const size_t mrow0 = (size_t)(b * SEQ + s0) * DMODEL + h * HD;
        const size_t mrow1 = mrow0 + 8 * DMODEL;
#pragma unroll
        for (int nt = 0; nt < 8; nt++) {
            const int d = nt * 8 + kq;
            __half h0, e0, h1, e1;
            split2(oa[nt][0] * il0, h0, e0);
            split2(oa[nt][1] * il0, h1, e1);
            *(uint32_t*)(outh + mrow0 + d) = pack_h2(h0, h1);
            *(uint32_t*)(outl + mrow0 + d) = pack_h2(e0, e1);
            split2(oa[nt][2] * il1, h0, e0);
            split2(oa[nt][3] * il1, h1, e1);
            *(uint32_t*)(outh + mrow1 + d) = pack_h2(h0, h1);
            *(uint32_t*)(outl + mrow1 + d) = pack_h2(e0, e1);
        }
    }
}

// ---------------------------------------------------------------------------
extern "C" void kernel_launch(void* const* d_in, const int* in_sizes, int n_in,
                              void* d_out, int out_size)
{
    const float* x     = (const float*)d_in[0];
    const float* w_qkv = (const float*)d_in[1];
    const float* w_out = (const float*)d_in[2];
    float* out = (float*)d_out;

    __half *xh, *xl, *wqh, *woh, *ah, *al, *qh, *ql, *kh, *vh;
    float2* rope_tab;
    cudaGetSymbolAddress((void**)&xh,  g_xh);
    cudaGetSymbolAddress((void**)&xl,  g_xl);
    cudaGetSymbolAddress((void**)&wqh, g_wqh);
    cudaGetSymbolAddress((void**)&woh, g_woh);
    cudaGetSymbolAddress((void**)&ah,  g_ah);
    cudaGetSymbolAddress((void**)&al,  g_al);
    cudaGetSymbolAddress((void**)&qh,  g_qh);
    cudaGetSymbolAddress((void**)&ql,  g_ql);
    cudaGetSymbolAddress((void**)&kh,  g_kh);
    cudaGetSymbolAddress((void**)&vh,  g_vh);
    cudaGetSymbolAddress((void**)&rope_tab, g_rope_tab);

    cudaFuncSetAttribute(gemm_fp16x2_kernel<256>,
                         cudaFuncAttributeMaxDynamicSharedMemorySize, G_SMEM_256);
    cudaFuncSetAttribute(gemm_fp16x2_kernel<128>,
                         cudaFuncAttributeMaxDynamicSharedMemorySize, G_SMEM_128);
    cudaFuncSetAttribute(attn_tc_kernel,
                         cudaFuncAttributeMaxDynamicSharedMemorySize, AT_SMEM_B);

    // 1) fused prep: convert x + both weight transposes + rope table
    prep_kernel<<<PREP_BLOCKS, 256>>>(
        (const float4*)x, w_qkv, w_out,
        (uint2*)xh, (uint2*)xl, wqh, woh, rope_tab);

    // 2) QKV projection + fused RoPE/split epilogue (BM=256, 64x64 warp tiles)
    gemm_fp16x2_kernel<256><<<dim3(QKV_N / 128, M_ROWS / 256), 256, G_SMEM_256>>>(
        xh, xl, wqh, nullptr, qh, ql, kh, vh, M_ROWS, QKV_N, DMODEL, 1);

    // 3) Causal flash attention, paired q-tiles (writes out-proj A directly)
    attn_tc_kernel<<<dim3(SEQ / 256, BATCH * NH), 256, AT_SMEM_B>>>(
        qh, ql, kh, vh, ah, al);

    // 4) Output projection (BM=128, R15 config)
    gemm_fp16x2_kernel<128><<<dim3(DMODEL / 128, M_ROWS / 128), 256, G_SMEM_128>>>(
        ah, al, woh, out, nullptr, nullptr, nullptr, nullptr,
        M_ROWS, DMODEL, DMODEL, 0);
}

// round 17
// speedup vs baseline: 1.1137x; 1.1137x over previous
#include <cuda_runtime.h>
#include <cuda_fp16.h>
#include <math.h>
#include <stdint.h>

#define BATCH  2
#define SEQ    2048
#define DMODEL 1024
#define NH     16
#define HD     64
#define M_ROWS (BATCH * SEQ)    // 4096
#define QKV_N  (3 * DMODEL)     // 3072

// ---------------------------------------------------------------------------
// Device scratch (fp16 emulation: A-side split hi/lo, B-side hi only)
// ---------------------------------------------------------------------------
__device__ __half g_xh[M_ROWS * DMODEL];
__device__ __half g_xl[M_ROWS * DMODEL];
__device__ __half g_wqh[QKV_N * DMODEL];   // [N,K] transposed, hi only
__device__ __half g_woh[DMODEL * DMODEL];  // [N,K] transposed, hi only
__device__ __half g_ah[M_ROWS * DMODEL];   // attention out hi (A of out-proj)
__device__ __half g_al[M_ROWS * DMODEL];

#define QKV_ELEMS (BATCH * NH * SEQ * HD)
__device__ __half g_qh[QKV_ELEMS];  // [B,H,S,hd], pre-scaled by 1/8
__device__ __half g_ql[QKV_ELEMS];
__device__ __half g_kh[QKV_ELEMS];  // hi only (B operand of QK^T)
__device__ __half g_vh[QKV_ELEMS];  // hi only (B operand of PV)

__device__ float2 g_rope_tab[SEQ * 32];    // (cos, sin) per (s, j)

// ---------------------------------------------------------------------------
// Baseline-PTX helpers
// ---------------------------------------------------------------------------
__device__ __forceinline__ uint32_t smem_u32(const void* p) {
    uint32_t a;
    asm("{ .reg .u64 t; cvta.to.shared.u64 t, %1; cvt.u32.u64 %0, t; }"
        : "=r"(a) : "l"(p));
    return a;
}

#define CP_ASYNC_16(smem, gptr) \
    asm volatile("cp.async.cg.shared.global [%0], [%1], 16;\n" \
        :: "r"(smem), "l"(gptr))
#define CP_ASYNC_COMMIT() asm volatile("cp.async.commit_group;\n")
#define CP_ASYNC_WAIT(n)  asm volatile("cp.async.wait_group %0;\n" :: "n"(n))

__device__ __forceinline__ void ldsm_x4(uint32_t* r, uint32_t addr) {
    asm volatile("ldmatrix.sync.aligned.m8n8.x4.shared.b16 {%0,%1,%2,%3}, [%4];\n"
        : "=r"(r[0]), "=r"(r[1]), "=r"(r[2]), "=r"(r[3]) : "r"(addr));
}
__device__ __forceinline__ void ldsm_x4_t(uint32_t* r, uint32_t addr) {
    asm volatile("ldmatrix.sync.aligned.m8n8.x4.trans.shared.b16 {%0,%1,%2,%3}, [%4];\n"
        : "=r"(r[0]), "=r"(r[1]), "=r"(r[2]), "=r"(r[3]) : "r"(addr));
}

// D(f32) += A(f16) * B(f16): m16n8k16
__device__ __forceinline__ void mma16816(float* d, const uint32_t* a, const uint32_t* b) {
    asm volatile(
        "mma.sync.aligned.m16n8k16.row.col.f32.f16.f16.f32 "
        "{%0,%1,%2,%3}, {%4,%5,%6,%7}, {%8,%9}, {%0,%1,%2,%3};\n"
        : "+f"(d[0]), "+f"(d[1]), "+f"(d[2]), "+f"(d[3])
        : "r"(a[0]), "r"(a[1]), "r"(a[2]), "r"(a[3]), "r"(b[0]), "r"(b[1]));
}

// 128B-row swizzle: 16B chunk (0..7) xor bits [2:0] of row
__device__ __forceinline__ uint32_t aswz(int row, int chunk) {
    return (uint32_t)(row * 128 + ((chunk ^ (row & 7)) << 4));
}

// ---------------------------------------------------------------------------
// fp32 -> (hi, lo) fp16 split helpers
// ---------------------------------------------------------------------------
__device__ __forceinline__ void split2(float x, __half& h, __half& l) {
    h = __float2half(x);
    l = __float2half(x - __half2float(h));
}
__device__ __forceinline__ uint32_t pack_h2(__half a, __half b) {
    __half2 t; t.x = a; t.y = b;
    return *(uint32_t*)&t;
}

// ---------------------------------------------------------------------------
// Fused prep (unchanged)
// ---------------------------------------------------------------------------
#define PREP_CONV_BLOCKS  4096
#define PREP_TRANS_BLOCKS 4096
#define PREP_ROPE_BLOCKS  256
#define PREP_BLOCKS (PREP_CONV_BLOCKS + PREP_TRANS_BLOCKS + PREP_ROPE_BLOCKS)

__global__ void __launch_bounds__(256)
prep_kernel(const float4* __restrict__ x4,
            const float* __restrict__ Wq, const float* __restrict__ Wo,
            uint2* __restrict__ xh, uint2* __restrict__ xl,
            __half* __restrict__ Tq, __half* __restrict__ To,
            float2* __restrict__ tab)
{
    const int blk = blockIdx.x;
    const int tid = threadIdx.x;

    if (blk < PREP_CONV_BLOCKS) {
        int i = blk * 256 + tid;
        float4 v = x4[i];
        __half h0, l0, h1, l1, h2, l2, h3, l3;
        split2(v.x, h0, l0); split2(v.y, h1, l1);
        split2(v.z, h2, l2); split2(v.w, h3, l3);
        xh[i] = make_uint2(pack_h2(h0, h1), pack_h2(h2, h3));
        xl[i] = make_uint2(pack_h2(l0, l1), pack_h2(l2, l3));
    } else if (blk < PREP_CONV_BLOCKS + PREP_TRANS_BLOCKS) {
        __shared__ float tile[32][33];
        const int t = blk - PREP_CONV_BLOCKS;
        const int tile_n = t & 127;
        const int tile_k = t >> 7;
        const int tx = tid & 31;
        const int ty0 = tid >> 5;
        const int n = tile_n * 32 + tx;
#pragma unroll
        for (int r = 0; r < 4; r++) {
            const int ty = ty0 + r * 8;
            const int k = tile_k * 32 + ty;
            float v = (n < QKV_N) ? Wq[(size_t)k * QKV_N + n]
                                  : Wo[(size_t)k * DMODEL + (n - QKV_N)];
            tile[ty][tx] = v;
        }
        __syncthreads();
#pragma unroll
        for (int r = 0; r < 4; r++) {
            const int ty = ty0 + r * 8;
            const int nt = tile_n * 32 + ty;
            const int kt = tile_k * 32 + tx;
            __half hv = __float2half(tile[tx][ty]);
            if (nt < QKV_N) Tq[(size_t)nt * DMODEL + kt] = hv;
            else            To[(size_t)(nt - QKV_N) * DMODEL + kt] = hv;
        }
    } else {
        int i = (blk - PREP_CONV_BLOCKS - PREP_TRANS_BLOCKS) * 256 + tid;
        int j = i & 31, s = i >> 5;
        float inv_freq = powf(10000.0f, -(float)j * (1.0f / 32.0f));
        float sn, cs;
        sincosf((float)s * inv_freq, &sn, &cs);
        tab[i] = make_float2(cs, sn);
    }
}

// ---------------------------------------------------------------------------
// Tensor-core GEMM (exact R15 config): 256 threads = 8 warps (4m x 2n),
// warp tile 32x64, CTA 128x128, BK=64, double-buffer, 128 regs, 2 CTAs/SM.
// mode 0: store fp32 C.  mode 1: fused in-register RoPE/split epilogue.
// ---------------------------------------------------------------------------
#define G_BK 64
#define G_TILE_B  (128 * 128)           // 16384
#define G_STAGE_B (3 * G_TILE_B)        // 49152: Ahi, Alo, Bh
#define G_SMEM_BYTES (2 * G_STAGE_B)    // 98304

__global__ void __launch_bounds__(256)
gemm_fp16x2_kernel(const __half* __restrict__ Ahi,
                   const __half* __restrict__ Alo,
                   const __half* __restrict__ Bh,
                   float* __restrict__ C,
                   __half* __restrict__ qh, __half* __restrict__ ql,
                   __half* __restrict__ kh, __half* __restrict__ vh,
                   int M, int N, int K, int mode)
{
    extern __shared__ __align__(128) char dsm[];
    const uint32_t smem_base = smem_u32(dsm);

    const int tid = threadIdx.x;
    const int wid = tid >> 5;
    const int lane = tid & 31;
    const int warp_m = wid >> 1;
    const int warp_n = wid & 1;
    const int m0 = blockIdx.y * 128;
    const int n0 = blockIdx.x * 128;

    const __half* gsrc[3] = {Ahi, Alo, Bh};

    float acc[2][8][4];
#pragma unroll
    for (int i = 0; i < 2; i++)
#pragma unroll
        for (int j = 0; j < 8; j++)
#pragma unroll
            for (int c = 0; c < 4; c++) acc[i][j][c] = 0.f;

    const int nchunk = K / G_BK;       // 16

    auto issue = [&](int ci) {
        const int k0 = ci * G_BK;
        const uint32_t st = smem_base + (ci & 1) * G_STAGE_B;
#pragma unroll
        for (int i = 0; i < 12; i++) {
            const int tile = i >> 2;
            const int idx = ((i & 3) << 8) | tid;
            const int r = idx >> 3;
            const int c = idx & 7;
            const int grow = (tile < 2 ? m0 : n0) + r;
            const __half* gp = gsrc[tile] + (size_t)grow * K + k0 + c * 8;
            CP_ASYNC_16(st + tile * G_TILE_B + aswz(r, c), gp);
        }
        CP_ASYNC_COMMIT();
    };

    issue(0);

    const int a_row_off = (lane & 15);
    const int a_coff    = (lane >> 4) & 1;
    const int b_row_off = ((lane & 16) >> 1) + (lane & 7);
    const int b_coff    = (lane & 8) >> 3;

#pragma unroll 1
    for (int ci = 0; ci < nchunk; ci++) {
        CP_ASYNC_WAIT(0);
        __syncthreads();
        if (ci + 1 < nchunk) issue(ci + 1);

        const uint32_t st = smem_base + (ci & 1) * G_STAGE_B;
        const uint32_t sAhi = st;
        const uint32_t sAlo = st + G_TILE_B;
        const uint32_t sBh  = st + 2 * G_TILE_B;

#pragma unroll
        for (int ks = 0; ks < 4; ks++) {
            uint32_t ahi[2][4], alo[2][4];
#pragma unroll
            for (int mt = 0; mt < 2; mt++) {
                const int ar = warp_m * 32 + mt * 16 + a_row_off;
                const uint32_t aoff = aswz(ar, ks * 2 + a_coff);
                ldsm_x4(ahi[mt], sAhi + aoff);
                ldsm_x4(alo[mt], sAlo + aoff);
            }
#pragma unroll
            for (int ntp = 0; ntp < 4; ntp++) {
                const int br = warp_n * 64 + ntp * 16 + b_row_off;
                const uint32_t boff = aswz(br, ks * 2 + b_coff);
                uint32_t bh4[4];
                ldsm_x4(bh4, sBh + boff);
#pragma unroll
                for (int mt = 0; mt < 2; mt++)
#pragma unroll
                    for (int j = 0; j < 2; j++) {
                        float* d = acc[mt][2 * ntp + j];
                        mma16816(d, ahi[mt], &bh4[2 * j]);
                        mma16816(d, alo[mt], &bh4[2 * j]);
                    }
            }
        }
    }

    const int quad = lane >> 2;
    const int tq = lane & 3;

    if (mode == 0) {
        float* Cw = C + (size_t)(m0 + warp_m * 32) * N + n0 + warp_n * 64;
#pragma unroll
        for (int mt = 0; mt < 2; mt++)
#pragma unroll
            for (int nt = 0; nt < 8; nt++) {
                const int r = mt * 16 + quad;
                const int c = nt * 8 + tq * 2;
                *(float2*)(Cw + (size_t)r * N + c) =
                    make_float2(acc[mt][nt][0], acc[mt][nt][1]);
                *(float2*)(Cw + (size_t)(r + 8) * N + c) =
                    make_float2(acc[mt][nt][2], acc[mt][nt][3]);
            }
        return;
    }

    // ---- mode 1: fused RoPE + split epilogue for QKV ----
    const int ng0 = n0 + warp_n * 64;
    const int sec = ng0 >> 10;
    const int hh  = (ng0 & 1023) >> 6;
    __half* ph = (sec == 0) ? qh : (sec == 1) ? kh : vh;

#pragma unroll
    for (int mt = 0; mt < 2; mt++) {
#pragma unroll
        for (int half = 0; half < 2; half++) {
            const int r_g = m0 + warp_m * 32 + mt * 16 + quad + half * 8;
            const int b = r_g >> 11, s = r_g & 2047;
            const size_t dst = ((size_t)((b * NH + hh) * SEQ) + s) * HD;
            const float2* trow = g_rope_tab + s * 32;
#pragma unroll
            for (int nt = 0; nt < 8; nt++) {
                const int d0 = nt * 8 + tq * 2;
                float v0 = acc[mt][nt][half * 2 + 0];
                float v1 = acc[mt][nt][half * 2 + 1];
                float r0, r1;
                if (sec < 2) {
                    const float p0 = acc[mt][nt ^ 4][half * 2 + 0];
                    const float p1 = acc[mt][nt ^ 4][half * 2 + 1];
                    const int j0 = d0 & 31;
                    const float2 t0 = trow[j0];
                    const float2 t1 = trow[j0 + 1];
                    if (nt < 4) { r0 = v0 * t0.x - p0 * t0.y; r1 = v1 * t1.x - p1 * t1.y; }
                    else        { r0 = v0 * t0.x + p0 * t0.y; r1 = v1 * t1.x + p1 * t1.y; }
                    if (sec == 0) { r0 *= 0.125f; r1 *= 0.125f; }
                } else { r0 = v0; r1 = v1; }
                if (sec == 0) {
                    __half h0, e0, h1, e1;
                    split2(r0, h0, e0);
                    split2(r1, h1, e1);
                    *(uint32_t*)(qh + dst + d0) = pack_h2(h0, h1);
                    *(uint32_t*)(ql + dst + d0) = pack_h2(e0, e1);
                } else {
                    *(uint32_t*)(ph + dst + d0) =
                        pack_h2(__float2half(r0), __float2half(r1));
                }
            }
        }
    }
}

// ---------------------------------------------------------------------------
// Tensor-core causal flash attention (fp16 x 2-term emulation).
// 256 threads = 8 warps, q-tile 128 (16 rows/warp).
// Key tiles of 128, processed as two 64-key halves sharing ONE load+barrier
// (halves barrier/wait/commit count vs R15). 3-stage cp.async pipeline.
// ---------------------------------------------------------------------------
#define AT_TILE_B  (128 * 128)            // 16384 per K or V tile (128 keys)
#define AT_STAGE_B (2 * AT_TILE_B)        // 32768: Kh, Vh
#define AT_STAGES  3
#define AT_SMEM_B  (AT_STAGES * AT_STAGE_B)  // 98304

__global__ void __launch_bounds__(256)
attn_tc_kernel(const __half* __restrict__ qh, const __half* __restrict__ ql,
               const __half* __restrict__ kh, const __half* __restrict__ vh,
               __half* __restrict__ outh, __half* __restrict__ outl)
{
    extern __shared__ __align__(128) char dsm[];
    const uint32_t sb = smem_u32(dsm);

    const int bh = blockIdx.y;
    const int tid = threadIdx.x;
    const int wid = tid >> 5;
    const int lane = tid & 31;
    const int kq = (lane & 3) * 2;
    const size_t base = (size_t)bh * SEQ * HD;

    const __half* khp = kh + base;
    const __half* vhp = vh + base;

    // one issue = 128 keys of K + V (16 KB each): 8 cp.async per thread
    auto issue = [&](int kt) {
        const uint32_t st = sb + (kt % AT_STAGES) * AT_STAGE_B;
        const __half* srcs[2] = {khp, vhp};
        const int kr0 = kt * 128;
#pragma unroll
        for (int t = 0; t < 2; t++) {
#pragma unroll
            for (int i = 0; i < 4; i++) {
                int c = i * 256 + tid;           // 0..1023
                int row = c >> 3, col = c & 7;
                CP_ASYNC_16(st + t * AT_TILE_B + aswz(row, col),
                            srcs[t] + (size_t)(kr0 + row) * HD + col * 8);
            }
        }
        CP_ASYNC_COMMIT();
    };

    const int b_row = ((lane & 16) >> 1) + (lane & 7);
    const int b_coff = (lane & 8) >> 3;
    const int vg    = lane >> 3;
    const int rloc = wid * 16 + (lane >> 2);

#pragma unroll 1
    for (int ps = 0; ps < 2; ps++) {
        const int qt = ps ? (int)blockIdx.x : (SEQ / 128 - 1 - (int)blockIdx.x);
        const int grow = qt * 128 + rloc;

        uint32_t qfh[4][4], qfl[4][4];
#pragma unroll
        for (int kc = 0; kc < 4; kc++) {
            size_t o = base + (size_t)grow * HD + kc * 16 + kq;
            qfh[kc][0] = *(const uint32_t*)(qh + o);
            qfh[kc][1] = *(const uint32_t*)(qh + o + 8 * HD);
            qfh[kc][2] = *(const uint32_t*)(qh + o + 8);
            qfh[kc][3] = *(const uint32_t*)(qh + o + 8 * HD + 8);
            qfl[kc][0] = *(const uint32_t*)(ql + o);
            qfl[kc][1] = *(const uint32_t*)(ql + o + 8 * HD);
            qfl[kc][2] = *(const uint32_t*)(ql + o + 8);
            qfl[kc][3] = *(const uint32_t*)(ql + o + 8 * HD + 8);
        }

        float oa[8][4];
#pragma unroll
        for (int i = 0; i < 8; i++)
#pragma unroll
            for (int c = 0; c < 4; c++) oa[i][c] = 0.f;
        float m0 = -INFINITY, m1 = -INFINITY, l0 = 0.f, l1 = 0.f;

        const int nkt = qt + 1;              // 128-key tiles: 0 .. qt

        __syncthreads();                     // smem safe for reuse across passes
        issue(0);
        if (nkt > 1) issue(1);

#pragma unroll 1
        for (int kt = 0; kt < nkt; kt++) {
            if (kt + 1 < nkt) { CP_ASYNC_WAIT(1); } else { CP_ASYNC_WAIT(0); }
            __syncthreads();
            if (kt + 2 < nkt) issue(kt + 2);

            const uint32_t st  = sb + (kt % AT_STAGES) * AT_STAGE_B;
            const uint32_t sKh = st;
            const uint32_t sVh = st + AT_TILE_B;
            const int wrow_min = qt * 128 + wid * 16;

#pragma unroll 1
            for (int half = 0; half < 2; half++) {
                const int tile_k0 = kt * 128 + half * 64;
                const bool full_skip = tile_k0 > wrow_min + 15;
                const bool need_mask = !full_skip && (tile_k0 + 63 > wrow_min);
                if (full_skip) continue;

                const int hrow = half * 64;       // row offset inside smem tile

                // ---- S = Q @ K^T (2-term) ----
                float sacc[8][4];
#pragma unroll
                for (int i = 0; i < 8; i++)
#pragma unroll
                    for (int c = 0; c < 4; c++) sacc[i][c] = 0.f;

#pragma unroll
                for (int kc = 0; kc < 4; kc++) {
#pragma unroll
                    for (int np = 0; np < 4; np++) {
                        const int krow = hrow + np * 16 + b_row;
                        const uint32_t addr = aswz(krow, kc * 2 + b_coff);
                        uint32_t bh4[4];
                        ldsm_x4(bh4, sKh + addr);
#pragma unroll
                        for (int j = 0; j < 2; j++) {
                            float* d = sacc[2 * np + j];
                            mma16816(d, qfh[kc], &bh4[2 * j]);
                            mma16816(d, qfl[kc], &bh4[2 * j]);
                        }
                    }
                }

                // ---- causal mask (global indices) ----
                if (need_mask) {
#pragma unroll
                    for (int nt = 0; nt < 8; nt++) {
                        const int colg = tile_k0 + nt * 8 + kq;
                        if (colg > grow)         sacc[nt][0] = -INFINITY;
                        if (colg + 1 > grow)     sacc[nt][1] = -INFINITY;
                        if (colg > grow + 8)     sacc[nt][2] = -INFINITY;
                        if (colg + 1 > grow + 8) sacc[nt][3] = -INFINITY;
                    }
                }

                // ---- online softmax ----
                float rm0 = -INFINITY, rm1 = -INFINITY;
#pragma unroll
                for (int nt = 0; nt < 8; nt++) {
                    rm0 = fmaxf(rm0, fmaxf(sacc[nt][0], sacc[nt][1]));
                    rm1 = fmaxf(rm1, fmaxf(sacc[nt][2], sacc[nt][3]));
                }
                rm0 = fmaxf(rm0, __shfl_xor_sync(0xffffffffu, rm0, 1));
                rm0 = fmaxf(rm0, __shfl_xor_sync(0xffffffffu, rm0, 2));
                rm1 = fmaxf(rm1, __shfl_xor_sync(0xffffffffu, rm1, 1));
                rm1 = fmaxf(rm1, __shfl_xor_sync(0xffffffffu, rm1, 2));

                float mn0 = fmaxf(m0, rm0), mn1 = fmaxf(m1, rm1);
                float c0 = __expf(m0 - mn0), c1 = __expf(m1 - mn1);
                m0 = mn0; m1 = mn1;
                l0 *= c0; l1 *= c1;
#pragma unroll
                for (int nt = 0; nt < 8; nt++) {
                    oa[nt][0] *= c0; oa[nt][1] *= c0;
                    oa[nt][2] *= c1; oa[nt][3] *= c1;
                }

                // ---- P = exp(S - m) per 16-key group; O += P @ V (2-term) ----
                float ps0 = 0.f, ps1 = 0.f;
#pragma unroll
                for (int kc2 = 0; kc2 < 4; kc2++) {
                    uint32_t pfh[4], pfl[4];
#pragma unroll
                    for (int j = 0; j < 2; j++) {
                        const int t = 2 * kc2 + j;
                        float p0 = __expf(sacc[t][0] - m0);
                        float p1 = __expf(sacc[t][1] - m0);
                        float p2 = __expf(sacc[t][2] - m1);
                        float p3 = __expf(sacc[t][3] - m1);
                        ps0 += p0 + p1; ps1 += p2 + p3;
                        __half h0, e0, h1, e1, h2, e2, h3, e3;
                        split2(p0, h0, e0); split2(p1, h1, e1);
                        split2(p2, h2, e2); split2(p3, h3, e3);
                        pfh[2 * j]     = pack_h2(h0, h1);
                        pfh[2 * j + 1] = pack_h2(h2, h3);
                        pfl[2 * j]     = pack_h2(e0, e1);
                        pfl[2 * j + 1] = pack_h2(e2, e3);
                    }
#pragma unroll
                    for (int dp = 0; dp < 4; dp++) {
                        const int vrow = hrow + kc2 * 16 + (lane & 7) + ((vg & 1) << 3);
                        const uint32_t addr = aswz(vrow, dp * 2 + (vg >> 1));
                        uint32_t bvh[4];
                        ldsm_x4_t(bvh, sVh + addr);
#pragma unroll
                        for (int j = 0; j < 2; j++) {
                            float* d = oa[2 * dp + j];
                            mma16816(d, pfh, &bvh[2 * j]);
                            mma16816(d, pfl, &bvh[2 * j]);
                        }
                    }
                }
                ps0 += __shfl_xor_sync(0xffffffffu, ps0, 1);
                ps0 += __shfl_xor_sync(0xffffffffu, ps0, 2);
                ps1 += __shfl_xor_sync(0xffffffffu, ps1, 1);
                ps1 += __shfl_xor_sync(0xffffffffu, ps1, 2);
                l0 += ps0; l1 += ps1;
            }
        }

        // ---- epilogue: normalize, split, write [B*S, H*hd] fp16 hi/lo ----
        const float il0 = 1.0f / l0, il1 = 1.0f / l1;
        const int b = bh >> 4, h = bh & 15;
        const int s0 = qt * 128 + wid * 16 + (lane >> 2);
        const size_t mrow0 = (size_t)(b * SEQ + s0) * DMODEL + h * HD;
        const size_t mrow1 = mrow0 + 8 * DMODEL;
#pragma unroll
        for (int nt = 0; nt < 8; nt++) {
            const int d = nt * 8 + kq;
            __half h0, e0, h1, e1;
            split2(oa[nt][0] * il0, h0, e0);
            split2(oa[nt][1] * il0, h1, e1);
            *(uint32_t*)(outh + mrow0 + d) = pack_h2(h0, h1);
            *(uint32_t*)(outl + mrow0 + d) = pack_h2(e0, e1);
            split2(oa[nt][2] * il1, h0, e0);
            split2(oa[nt][3] * il1, h1, e1);
            *(uint32_t*)(outh + mrow1 + d) = pack_h2(h0, h1);
            *(uint32_t*)(outl + mrow1 + d) = pack_h2(e0, e1);
        }
    }
}

// ---------------------------------------------------------------------------
extern "C" void kernel_launch(void* const* d_in, const int* in_sizes, int n_in,
                              void* d_out, int out_size)
{
    const float* x     = (const float*)d_in[0];
    const float* w_qkv = (const float*)d_in[1];
    const float* w_out = (const float*)d_in[2];
    float* out = (float*)d_out;

    __half *xh, *xl, *wqh, *woh, *ah, *al, *qh, *ql, *kh, *vh;
    float2* rope_tab;
    cudaGetSymbolAddress((void**)&xh,  g_xh);
    cudaGetSymbolAddress((void**)&xl,  g_xl);
    cudaGetSymbolAddress((void**)&wqh, g_wqh);
    cudaGetSymbolAddress((void**)&woh, g_woh);
    cudaGetSymbolAddress((void**)&ah,  g_ah);
    cudaGetSymbolAddress((void**)&al,  g_al);
    cudaGetSymbolAddress((void**)&qh,  g_qh);
    cudaGetSymbolAddress((void**)&ql,  g_ql);
    cudaGetSymbolAddress((void**)&kh,  g_kh);
    cudaGetSymbolAddress((void**)&vh,  g_vh);
    cudaGetSymbolAddress((void**)&rope_tab, g_rope_tab);

    cudaFuncSetAttribute(gemm_fp16x2_kernel,
                         cudaFuncAttributeMaxDynamicSharedMemorySize, G_SMEM_BYTES);
    cudaFuncSetAttribute(attn_tc_kernel,
                         cudaFuncAttributeMaxDynamicSharedMemorySize, AT_SMEM_B);

    // 1) fused prep: convert x + both weight transposes + rope table
    prep_kernel<<<PREP_BLOCKS, 256>>>(
        (const float4*)x, w_qkv, w_out,
        (uint2*)xh, (uint2*)xl, wqh, woh, rope_tab);

    // 2) QKV projection + fused RoPE/split epilogue (R15 config)
    gemm_fp16x2_kernel<<<dim3(QKV_N / 128, M_ROWS / 128), 256, G_SMEM_BYTES>>>(
        xh, xl, wqh, nullptr, qh, ql, kh, vh, M_ROWS, QKV_N, DMODEL, 1);

    // 3) Causal flash attention, paired q-tiles, 128-key tiles
    attn_tc_kernel<<<dim3(SEQ / 256, BATCH * NH), 256, AT_SMEM_B>>>(
        qh, ql, kh, vh, ah, al);

    // 4) Output projection (R15 config)
    gemm_fp16x2_kernel<<<dim3(DMODEL / 128, M_ROWS / 128), 256, G_SMEM_BYTES>>>(
        ah, al, woh, out, nullptr, nullptr, nullptr, nullptr,
        M_ROWS, DMODEL, DMODEL, 0);
}